// round 11
// baseline (speedup 1.0000x reference)
#include <cuda_runtime.h>
#include <cuda_bf16.h>

#define D 128
#define N_MAX 50000
#define TE_MAX 2400000   // G*E = 3 * 800000

// ---- device scratch (no allocations allowed) -------------------------------
__device__ float g_h[(size_t)N_MAX * D];          // 25.6 MB  projected features
__device__ int   g_counts[N_MAX];                 // per-dest-row edge counts
__device__ int   g_offsets[N_MAX + 1];            // exclusive scan
__device__ int   g_cursor[N_MAX];                 // fill cursors
__device__ int2  g_edges[TE_MAX];                 // packed {col, weight-bits}, 19.2 MB

// ---------------------------------------------------------------------------
// GEMM: H[n,d] = sum_k X[n,k] * W[d,k]
// 128x128 block tile, 256 threads, 8x8 register tile per thread.
// k-major smem so the inner loop uses LDS.128 (4 vector loads : 64 FFMA).
// ---------------------------------------------------------------------------
__global__ __launch_bounds__(256, 2) void gemm_xwT_kernel(
    const float* __restrict__ X, const float* __restrict__ W,
    float* __restrict__ H, int N)
{
    // k-major tiles, padded by 4 floats so row stride (132*4=528B) stays 16B-aligned
    __shared__ float Xs[16][132];
    __shared__ float Ws[16][132];

    const int tx = threadIdx.x & 15;    // col octet: cols tx*8 .. tx*8+7
    const int ty = threadIdx.x >> 4;    // row octet: rows ty*8 .. ty*8+7
    const int row0 = blockIdx.x * 128;

    float acc[8][8];
#pragma unroll
    for (int i = 0; i < 8; i++)
#pragma unroll
        for (int j = 0; j < 8; j++) acc[i][j] = 0.f;

    for (int k0 = 0; k0 < D; k0 += 16) {
        // load X tile 128 rows x 16 k (2048 floats = 512 float4, 2 per thread),
        // transposing to k-major in smem
#pragma unroll
        for (int l = 0; l < 2; l++) {
            int idx = threadIdx.x + l * 256;     // 0..511
            int r  = idx >> 2;                   // 0..127
            int c4 = (idx & 3) * 4;              // 0,4,8,12
            int gr = row0 + r;
            float4 v = make_float4(0.f, 0.f, 0.f, 0.f);
            if (gr < N) v = *(const float4*)&X[(size_t)gr * D + k0 + c4];
            Xs[c4 + 0][r] = v.x; Xs[c4 + 1][r] = v.y;
            Xs[c4 + 2][r] = v.z; Xs[c4 + 3][r] = v.w;
        }
        // load W tile 128 cols x 16 k, same transpose
#pragma unroll
        for (int l = 0; l < 2; l++) {
            int idx = threadIdx.x + l * 256;
            int r  = idx >> 2;
            int c4 = (idx & 3) * 4;
            float4 v = *(const float4*)&W[(size_t)r * D + k0 + c4];
            Ws[c4 + 0][r] = v.x; Ws[c4 + 1][r] = v.y;
            Ws[c4 + 2][r] = v.z; Ws[c4 + 3][r] = v.w;
        }
        __syncthreads();

#pragma unroll
        for (int k = 0; k < 16; k++) {
            float a[8], b[8];
            *(float4*)&a[0] = *(const float4*)&Xs[k][ty * 8];
            *(float4*)&a[4] = *(const float4*)&Xs[k][ty * 8 + 4];
            *(float4*)&b[0] = *(const float4*)&Ws[k][tx * 8];
            *(float4*)&b[4] = *(const float4*)&Ws[k][tx * 8 + 4];
#pragma unroll
            for (int i = 0; i < 8; i++)
#pragma unroll
                for (int j = 0; j < 8; j++) acc[i][j] += a[i] * b[j];
        }
        __syncthreads();
    }

#pragma unroll
    for (int i = 0; i < 8; i++) {
        int r = row0 + ty * 8 + i;
        if (r < N) {
            float4 lo = make_float4(acc[i][0], acc[i][1], acc[i][2], acc[i][3]);
            float4 hi = make_float4(acc[i][4], acc[i][5], acc[i][6], acc[i][7]);
            *(float4*)&H[(size_t)r * D + tx * 8]     = lo;
            *(float4*)&H[(size_t)r * D + tx * 8 + 4] = hi;
        }
    }
}

// ---------------------------------------------------------------------------
// 1) histogram of destination rows
// ---------------------------------------------------------------------------
__global__ __launch_bounds__(256) void hist_kernel(
    const int* __restrict__ rows, int total)
{
    int e = blockIdx.x * blockDim.x + threadIdx.x;
    if (e < total) atomicAdd(&g_counts[rows[e]], 1);
}

// ---------------------------------------------------------------------------
// 2) single-block exclusive scan over counts -> offsets (+cursor copy)
// ---------------------------------------------------------------------------
__global__ __launch_bounds__(1024) void scan_kernel(int n)
{
    __shared__ int warp_sums[32];
    __shared__ int s_carry;
    const int tid = threadIdx.x;
    if (tid == 0) s_carry = 0;
    __syncthreads();

    for (int base = 0; base < n; base += 1024) {
        int i = base + tid;
        int x = (i < n) ? g_counts[i] : 0;

        int v = x;
#pragma unroll
        for (int d = 1; d < 32; d <<= 1) {
            int t = __shfl_up_sync(0xFFFFFFFFu, v, d);
            if ((tid & 31) >= d) v += t;
        }
        if ((tid & 31) == 31) warp_sums[tid >> 5] = v;
        __syncthreads();
        if (tid < 32) {
            int ws = warp_sums[tid];
#pragma unroll
            for (int d = 1; d < 32; d <<= 1) {
                int t = __shfl_up_sync(0xFFFFFFFFu, ws, d);
                if (tid >= d) ws += t;
            }
            warp_sums[tid] = ws;
        }
        __syncthreads();

        int warp_excl = (tid >= 32) ? warp_sums[(tid >> 5) - 1] : 0;
        int incl = v + warp_excl + s_carry;
        int excl = incl - x;
        if (i < n) { g_offsets[i] = excl; g_cursor[i] = excl; }
        __syncthreads();
        if (tid == 1023) s_carry = incl;
        __syncthreads();
    }
    if (tid == 0) g_offsets[n] = s_carry;
}

// ---------------------------------------------------------------------------
// 3) fill: route each edge to its row's segment with gate folded into weight
// ---------------------------------------------------------------------------
__global__ __launch_bounds__(256) void fill_kernel(
    const int* __restrict__ rows, const int* __restrict__ cols,
    const float* __restrict__ vals, const float* __restrict__ alpha,
    int E, int total)
{
    int e = blockIdx.x * blockDim.x + threadIdx.x;
    if (e >= total) return;

    const int g = (e >= 2 * E) ? 2 : ((e >= E) ? 1 : 0);
    const float a = __ldg(alpha + g);
    const float gate = 1.f / (1.f + __expf(-a));
    const float w = gate * __ldg(vals + e);

    const int row = __ldg(rows + e);
    const int pos = atomicAdd(&g_cursor[row], 1);
    g_edges[pos] = make_int2(__ldg(cols + e), __float_as_int(w));
}

// ---------------------------------------------------------------------------
// 4) gather: one warp per destination row, lane = one float4 of the row.
// ---------------------------------------------------------------------------
__global__ __launch_bounds__(256) void gather_kernel(
    const float* __restrict__ H, float* __restrict__ out, int N)
{
    const int warp = (int)((blockIdx.x * (unsigned)blockDim.x + threadIdx.x) >> 5);
    const int lane = threadIdx.x & 31;
    if (warp >= N) return;

    const int start = __ldg(&g_offsets[warp]);
    const int end   = __ldg(&g_offsets[warp + 1]);

    float4 acc0 = make_float4(0.f, 0.f, 0.f, 0.f);
    float4 acc1 = make_float4(0.f, 0.f, 0.f, 0.f);

    for (int i = start; i < end; i += 32) {
        const int cnt = min(32, end - i);
        int2 ed = make_int2(0, 0);
        if (lane < cnt) ed = g_edges[i + lane];

        int j = 0;
        for (; j + 1 < cnt; j += 2) {
            int   c0 = __shfl_sync(0xFFFFFFFFu, ed.x, j);
            float w0 = __int_as_float(__shfl_sync(0xFFFFFFFFu, ed.y, j));
            int   c1 = __shfl_sync(0xFFFFFFFFu, ed.x, j + 1);
            float w1 = __int_as_float(__shfl_sync(0xFFFFFFFFu, ed.y, j + 1));
            float4 h0 = __ldg(((const float4*)(H + (size_t)c0 * D)) + lane);
            float4 h1 = __ldg(((const float4*)(H + (size_t)c1 * D)) + lane);
            acc0.x += w0 * h0.x; acc0.y += w0 * h0.y;
            acc0.z += w0 * h0.z; acc0.w += w0 * h0.w;
            acc1.x += w1 * h1.x; acc1.y += w1 * h1.y;
            acc1.z += w1 * h1.z; acc1.w += w1 * h1.w;
        }
        if (j < cnt) {
            int   c0 = __shfl_sync(0xFFFFFFFFu, ed.x, j);
            float w0 = __int_as_float(__shfl_sync(0xFFFFFFFFu, ed.y, j));
            float4 h0 = __ldg(((const float4*)(H + (size_t)c0 * D)) + lane);
            acc0.x += w0 * h0.x; acc0.y += w0 * h0.y;
            acc0.z += w0 * h0.z; acc0.w += w0 * h0.w;
        }
    }

    float4 r;
    r.x = acc0.x + acc1.x; r.y = acc0.y + acc1.y;
    r.z = acc0.z + acc1.z; r.w = acc0.w + acc1.w;
    ((float4*)(out + (size_t)warp * D))[lane] = r;
}

// ---------------------------------------------------------------------------
// Launch: fork GEMM onto a non-blocking side stream so it overlaps the
// memset->hist->scan->fill pipeline; join before the gather.
// Streams/events are host-side objects created per call (kernel_launch is
// only invoked twice: correctness + capture), no device allocation involved.
// ---------------------------------------------------------------------------
extern "C" void kernel_launch(void* const* d_in, const int* in_sizes, int n_in,
                              void* d_out, int out_size)
{
    const float* X     = (const float*)d_in[0];
    const float* W     = (const float*)d_in[1];
    const float* alpha = (const float*)d_in[2];
    const int*   rows  = (const int*)  d_in[3];
    const int*   cols  = (const int*)  d_in[4];
    const float* vals  = (const float*)d_in[5];
    float* out = (float*)d_out;

    const int N = in_sizes[0] / D;
    const int G = in_sizes[2];
    const int total_edges = in_sizes[3];
    const int E = total_edges / G;

    float* H;
    cudaGetSymbolAddress((void**)&H, g_h);
    int* counts;
    cudaGetSymbolAddress((void**)&counts, g_counts);

    cudaStream_t s2;
    cudaEvent_t ev_fork, ev_join;
    cudaStreamCreateWithFlags(&s2, cudaStreamNonBlocking);
    cudaEventCreateWithFlags(&ev_fork, cudaEventDisableTiming);
    cudaEventCreateWithFlags(&ev_join, cudaEventDisableTiming);

    // ---- fork: GEMM on side stream ----
    cudaEventRecord(ev_fork, 0);
    cudaStreamWaitEvent(s2, ev_fork, 0);
    gemm_xwT_kernel<<<(N + 127) / 128, 256, 0, s2>>>(X, W, H, N);
    cudaEventRecord(ev_join, s2);

    // ---- main stream: sort pipeline ----
    cudaMemsetAsync(counts, 0, (size_t)N * sizeof(int));
    hist_kernel<<<(total_edges + 255) / 256, 256>>>(rows, total_edges);
    scan_kernel<<<1, 1024>>>(N);
    fill_kernel<<<(total_edges + 255) / 256, 256>>>(rows, cols, vals, alpha,
                                                    E, total_edges);

    // ---- join, then gather ----
    cudaStreamWaitEvent(0, ev_join, 0);
    {
        int warps_per_block = 256 / 32;
        int blocks = (N + warps_per_block - 1) / warps_per_block;
        gather_kernel<<<blocks, 256>>>(H, out, N);
    }

    // host-side handles can be released immediately; captured graph keeps deps
    cudaEventDestroy(ev_fork);
    cudaEventDestroy(ev_join);
    cudaStreamDestroy(s2);
}

// round 12
// speedup vs baseline: 1.0245x; 1.0245x over previous
#include <cuda_runtime.h>
#include <cuda_bf16.h>

#define D 128
#define N_MAX 50000
#define TE_MAX 2400000   // G*E = 3 * 800000

// ---- device scratch (no allocations allowed) -------------------------------
__device__ float g_h[(size_t)N_MAX * D];          // 25.6 MB  projected features
__device__ int   g_counts[N_MAX];                 // per-dest-row edge counts
__device__ int   g_offsets[N_MAX + 1];            // exclusive scan
__device__ int   g_cursor[N_MAX];                 // fill cursors
__device__ int2  g_edges[TE_MAX];                 // packed {col, weight-bits}, 19.2 MB

// ---------------------------------------------------------------------------
// GEMM: H[n,d] = sum_k X[n,k] * W[d,k]
// 128x128 block tile, 256 threads, 8x8 register tile per thread.
// k-major smem so the inner loop uses LDS.128 (4 vector loads : 64 FFMA).
// ---------------------------------------------------------------------------
__global__ __launch_bounds__(256, 2) void gemm_xwT_kernel(
    const float* __restrict__ X, const float* __restrict__ W,
    float* __restrict__ H, int N)
{
    // k-major tiles, padded by 4 floats so row stride (132*4=528B) stays 16B-aligned
    __shared__ float Xs[16][132];
    __shared__ float Ws[16][132];

    const int tx = threadIdx.x & 15;    // col octet: cols tx*8 .. tx*8+7
    const int ty = threadIdx.x >> 4;    // row octet: rows ty*8 .. ty*8+7
    const int row0 = blockIdx.x * 128;

    float acc[8][8];
#pragma unroll
    for (int i = 0; i < 8; i++)
#pragma unroll
        for (int j = 0; j < 8; j++) acc[i][j] = 0.f;

    for (int k0 = 0; k0 < D; k0 += 16) {
        // load X tile 128 rows x 16 k (2048 floats = 512 float4, 2 per thread),
        // transposing to k-major in smem
#pragma unroll
        for (int l = 0; l < 2; l++) {
            int idx = threadIdx.x + l * 256;     // 0..511
            int r  = idx >> 2;                   // 0..127
            int c4 = (idx & 3) * 4;              // 0,4,8,12
            int gr = row0 + r;
            float4 v = make_float4(0.f, 0.f, 0.f, 0.f);
            if (gr < N) v = *(const float4*)&X[(size_t)gr * D + k0 + c4];
            Xs[c4 + 0][r] = v.x; Xs[c4 + 1][r] = v.y;
            Xs[c4 + 2][r] = v.z; Xs[c4 + 3][r] = v.w;
        }
        // load W tile 128 cols x 16 k, same transpose
#pragma unroll
        for (int l = 0; l < 2; l++) {
            int idx = threadIdx.x + l * 256;
            int r  = idx >> 2;
            int c4 = (idx & 3) * 4;
            float4 v = *(const float4*)&W[(size_t)r * D + k0 + c4];
            Ws[c4 + 0][r] = v.x; Ws[c4 + 1][r] = v.y;
            Ws[c4 + 2][r] = v.z; Ws[c4 + 3][r] = v.w;
        }
        __syncthreads();

#pragma unroll
        for (int k = 0; k < 16; k++) {
            float a[8], b[8];
            *(float4*)&a[0] = *(const float4*)&Xs[k][ty * 8];
            *(float4*)&a[4] = *(const float4*)&Xs[k][ty * 8 + 4];
            *(float4*)&b[0] = *(const float4*)&Ws[k][tx * 8];
            *(float4*)&b[4] = *(const float4*)&Ws[k][tx * 8 + 4];
#pragma unroll
            for (int i = 0; i < 8; i++)
#pragma unroll
                for (int j = 0; j < 8; j++) acc[i][j] += a[i] * b[j];
        }
        __syncthreads();
    }

#pragma unroll
    for (int i = 0; i < 8; i++) {
        int r = row0 + ty * 8 + i;
        if (r < N) {
            float4 lo = make_float4(acc[i][0], acc[i][1], acc[i][2], acc[i][3]);
            float4 hi = make_float4(acc[i][4], acc[i][5], acc[i][6], acc[i][7]);
            *(float4*)&H[(size_t)r * D + tx * 8]     = lo;
            *(float4*)&H[(size_t)r * D + tx * 8 + 4] = hi;
        }
    }
}

// ---------------------------------------------------------------------------
// 1) histogram of destination rows
// ---------------------------------------------------------------------------
__global__ __launch_bounds__(256) void hist_kernel(
    const int* __restrict__ rows, int total)
{
    int e = blockIdx.x * blockDim.x + threadIdx.x;
    if (e < total) atomicAdd(&g_counts[rows[e]], 1);
}

// ---------------------------------------------------------------------------
// 2) single-block exclusive scan over counts -> offsets (+cursor copy)
// ---------------------------------------------------------------------------
__global__ __launch_bounds__(1024) void scan_kernel(int n)
{
    __shared__ int warp_sums[32];
    __shared__ int s_carry;
    const int tid = threadIdx.x;
    if (tid == 0) s_carry = 0;
    __syncthreads();

    for (int base = 0; base < n; base += 1024) {
        int i = base + tid;
        int x = (i < n) ? g_counts[i] : 0;

        int v = x;
#pragma unroll
        for (int d = 1; d < 32; d <<= 1) {
            int t = __shfl_up_sync(0xFFFFFFFFu, v, d);
            if ((tid & 31) >= d) v += t;
        }
        if ((tid & 31) == 31) warp_sums[tid >> 5] = v;
        __syncthreads();
        if (tid < 32) {
            int ws = warp_sums[tid];
#pragma unroll
            for (int d = 1; d < 32; d <<= 1) {
                int t = __shfl_up_sync(0xFFFFFFFFu, ws, d);
                if (tid >= d) ws += t;
            }
            warp_sums[tid] = ws;
        }
        __syncthreads();

        int warp_excl = (tid >= 32) ? warp_sums[(tid >> 5) - 1] : 0;
        int incl = v + warp_excl + s_carry;
        int excl = incl - x;
        if (i < n) { g_offsets[i] = excl; g_cursor[i] = excl; }
        __syncthreads();
        if (tid == 1023) s_carry = incl;
        __syncthreads();
    }
    if (tid == 0) g_offsets[n] = s_carry;
}

// ---------------------------------------------------------------------------
// 3) fill: route each edge to its row's segment with gate folded into weight
// ---------------------------------------------------------------------------
__global__ __launch_bounds__(256) void fill_kernel(
    const int* __restrict__ rows, const int* __restrict__ cols,
    const float* __restrict__ vals, const float* __restrict__ alpha,
    int E, int total)
{
    int e = blockIdx.x * blockDim.x + threadIdx.x;
    if (e >= total) return;

    const int g = (e >= 2 * E) ? 2 : ((e >= E) ? 1 : 0);
    const float a = __ldg(alpha + g);
    const float gate = 1.f / (1.f + __expf(-a));
    const float w = gate * __ldg(vals + e);

    const int row = __ldg(rows + e);
    const int pos = atomicAdd(&g_cursor[row], 1);
    g_edges[pos] = make_int2(__ldg(cols + e), __float_as_int(w));
}

// ---------------------------------------------------------------------------
// 4) gather: one warp per destination row, lane = one float4 of the row.
// ---------------------------------------------------------------------------
__global__ __launch_bounds__(256) void gather_kernel(
    const float* __restrict__ H, float* __restrict__ out, int N)
{
    const int warp = (int)((blockIdx.x * (unsigned)blockDim.x + threadIdx.x) >> 5);
    const int lane = threadIdx.x & 31;
    if (warp >= N) return;

    const int start = __ldg(&g_offsets[warp]);
    const int end   = __ldg(&g_offsets[warp + 1]);

    float4 acc0 = make_float4(0.f, 0.f, 0.f, 0.f);
    float4 acc1 = make_float4(0.f, 0.f, 0.f, 0.f);

    for (int i = start; i < end; i += 32) {
        const int cnt = min(32, end - i);
        int2 ed = make_int2(0, 0);
        if (lane < cnt) ed = g_edges[i + lane];

        int j = 0;
        for (; j + 1 < cnt; j += 2) {
            int   c0 = __shfl_sync(0xFFFFFFFFu, ed.x, j);
            float w0 = __int_as_float(__shfl_sync(0xFFFFFFFFu, ed.y, j));
            int   c1 = __shfl_sync(0xFFFFFFFFu, ed.x, j + 1);
            float w1 = __int_as_float(__shfl_sync(0xFFFFFFFFu, ed.y, j + 1));
            float4 h0 = __ldg(((const float4*)(H + (size_t)c0 * D)) + lane);
            float4 h1 = __ldg(((const float4*)(H + (size_t)c1 * D)) + lane);
            acc0.x += w0 * h0.x; acc0.y += w0 * h0.y;
            acc0.z += w0 * h0.z; acc0.w += w0 * h0.w;
            acc1.x += w1 * h1.x; acc1.y += w1 * h1.y;
            acc1.z += w1 * h1.z; acc1.w += w1 * h1.w;
        }
        if (j < cnt) {
            int   c0 = __shfl_sync(0xFFFFFFFFu, ed.x, j);
            float w0 = __int_as_float(__shfl_sync(0xFFFFFFFFu, ed.y, j));
            float4 h0 = __ldg(((const float4*)(H + (size_t)c0 * D)) + lane);
            acc0.x += w0 * h0.x; acc0.y += w0 * h0.y;
            acc0.z += w0 * h0.z; acc0.w += w0 * h0.w;
        }
    }

    float4 r;
    r.x = acc0.x + acc1.x; r.y = acc0.y + acc1.y;
    r.z = acc0.z + acc1.z; r.w = acc0.w + acc1.w;
    ((float4*)(out + (size_t)warp * D))[lane] = r;
}

// ---------------------------------------------------------------------------
// Launch: fork GEMM onto a non-blocking side stream so it overlaps the
// memset->hist->scan->fill pipeline; join before the gather.
// Streams/events are host-side objects created per call (kernel_launch is
// only invoked twice: correctness + capture), no device allocation involved.
// ---------------------------------------------------------------------------
extern "C" void kernel_launch(void* const* d_in, const int* in_sizes, int n_in,
                              void* d_out, int out_size)
{
    const float* X     = (const float*)d_in[0];
    const float* W     = (const float*)d_in[1];
    const float* alpha = (const float*)d_in[2];
    const int*   rows  = (const int*)  d_in[3];
    const int*   cols  = (const int*)  d_in[4];
    const float* vals  = (const float*)d_in[5];
    float* out = (float*)d_out;

    const int N = in_sizes[0] / D;
    const int G = in_sizes[2];
    const int total_edges = in_sizes[3];
    const int E = total_edges / G;

    float* H;
    cudaGetSymbolAddress((void**)&H, g_h);
    int* counts;
    cudaGetSymbolAddress((void**)&counts, g_counts);

    cudaStream_t s2;
    cudaEvent_t ev_fork, ev_join;
    cudaStreamCreateWithFlags(&s2, cudaStreamNonBlocking);
    cudaEventCreateWithFlags(&ev_fork, cudaEventDisableTiming);
    cudaEventCreateWithFlags(&ev_join, cudaEventDisableTiming);

    // ---- fork: GEMM on side stream ----
    cudaEventRecord(ev_fork, 0);
    cudaStreamWaitEvent(s2, ev_fork, 0);
    gemm_xwT_kernel<<<(N + 127) / 128, 256, 0, s2>>>(X, W, H, N);
    cudaEventRecord(ev_join, s2);

    // ---- main stream: sort pipeline ----
    cudaMemsetAsync(counts, 0, (size_t)N * sizeof(int));
    hist_kernel<<<(total_edges + 255) / 256, 256>>>(rows, total_edges);
    scan_kernel<<<1, 1024>>>(N);
    fill_kernel<<<(total_edges + 255) / 256, 256>>>(rows, cols, vals, alpha,
                                                    E, total_edges);

    // ---- join, then gather ----
    cudaStreamWaitEvent(0, ev_join, 0);
    {
        int warps_per_block = 256 / 32;
        int blocks = (N + warps_per_block - 1) / warps_per_block;
        gather_kernel<<<blocks, 256>>>(H, out, N);
    }

    // host-side handles can be released immediately; captured graph keeps deps
    cudaEventDestroy(ev_fork);
    cudaEventDestroy(ev_join);
    cudaStreamDestroy(s2);
}